// round 13
// baseline (speedup 1.0000x reference)
#include <cuda_runtime.h>

// StreamNet_K3_S1: fused halo-concat + 3x3 VALID conv + bias.
// x:[8,32,256,256] rbuf:[8,32,256,2] bbuf:[8,32,2,258] W:[32,32,3,3] bias:[32]
// out:[8,32,256,256]
//
// R12: row-streaming accumulation. One 6-float input row live at a time
// (was: 3x6 sliding window) -> live regs ~58, no spills at the
// __launch_bounds__(256,4) 64-reg cap. Same FMA count, same LDS traffic.

#define BATCH 8
#define CH 32
#define P 256
#define PP (P + 2)

#define TH 8              // output rows per block
#define TW 32             // output cols per block
#define IN_H (TH + 2)     // 10 padded rows in tile
#define IN_W (TW + 2)     // 34 padded cols in tile
#define IN_WP 36          // smem row stride (floats), keeps 16B alignment

#define SMEM_IN_FLOATS (CH * IN_H * IN_WP)   // 11520
#define SMEM_BYTES (SMEM_IN_FLOATS * 4)      // 46080 B -> 4 CTAs/SM

__global__ __launch_bounds__(256, 4)
void streamnet_conv3x3_kernel(const float* __restrict__ x,
                              const float* __restrict__ rbuf,
                              const float* __restrict__ bbuf,
                              const float* __restrict__ Wt,
                              const float* __restrict__ bias,
                              float* __restrict__ out)
{
    extern __shared__ float smem[];
    float* sIn = smem;                       // [CH][IN_H][IN_WP]

    const int tid   = threadIdx.x;
    const int b     = blockIdx.z;
    const int r0    = blockIdx.y * TH;       // output row base
    const int c0blk = blockIdx.x * TW;       // output col base

    // ---- load padded input tile: 32ci x 10 x 34, halo-mapped ----
    for (int t = tid; t < CH * IN_H * IN_W; t += 256) {
        int ci   = t / (IN_H * IN_W);
        int rem  = t - ci * (IN_H * IN_W);
        int y    = rem / IN_W;
        int xcol = rem - y * IN_W;
        int pr   = r0 + y;                   // padded row  [0, 258)
        int pc   = c0blk + xcol;             // padded col  [0, 258)
        float v;
        if (pr < 2) {
            v = bbuf[((b * CH + ci) * 2 + pr) * PP + pc];
        } else {
            int xr = pr - 2;
            if (pc < 2) {
                v = rbuf[((b * CH + ci) * P + xr) * 2 + pc];
            } else {
                int xc = pc - 2;
                v = (xc == P - 1) ? 0.0f
                                  : x[((size_t)(b * CH + ci) * P + xr) * P + xc];
            }
        }
        sIn[ci * (IN_H * IN_WP) + y * IN_WP + xcol] = v;
    }
    __syncthreads();

    // ---- compute: each thread = 1 c_out, 8 rows x 4 cols ----
    const int co = tid >> 3;
    const int c0 = (tid & 7) * 4;            // col offset within tile

    float acc[TH][4];
    const float bv = __ldg(bias + co);
    #pragma unroll
    for (int r = 0; r < TH; r++)
        #pragma unroll
        for (int c = 0; c < 4; c++)
            acc[r][c] = bv;

    // weights straight from global: 36KB total, shared by all 2048 blocks ->
    // L1/L2 resident after wave 1; 8 threads/warp share each address.
    const float* wbase = Wt + co * (CH * 9);

    #pragma unroll 1
    for (int ci = 0; ci < CH; ci++) {
        const float* ib = sIn + ci * (IN_H * IN_WP) + c0;

        float w[9];
        #pragma unroll
        for (int k = 0; k < 9; k++) w[k] = __ldg(wbase + ci * 9 + k);

        // row-streaming: padded input row y feeds output rows y-2..y
        // (out r uses padded rows r+kh, kh=0..2 => r = y - kh)
        #pragma unroll
        for (int y = 0; y < IN_H; y++) {
            float row[6];
            {
                const float* rp = ib + y * IN_WP;     // 16B-aligned
                float4 t4 = *reinterpret_cast<const float4*>(rp);
                float2 t2 = *reinterpret_cast<const float2*>(rp + 4);
                row[0] = t4.x; row[1] = t4.y; row[2] = t4.z; row[3] = t4.w;
                row[4] = t2.x; row[5] = t2.y;
            }
            #pragma unroll
            for (int kh = 0; kh < 3; kh++) {
                const int r = y - kh;                 // compile-time resolved
                if (r >= 0 && r < TH) {
                    #pragma unroll
                    for (int kw = 0; kw < 3; kw++) {
                        const float wv = w[kh * 3 + kw];
                        #pragma unroll
                        for (int c = 0; c < 4; c++)
                            acc[r][c] = fmaf(row[c + kw], wv, acc[r][c]);
                    }
                }
            }
        }
    }

    // ---- store: float4 per row, contiguous 128B per 8-thread group ----
    #pragma unroll
    for (int r = 0; r < TH; r++) {
        float4 v = make_float4(acc[r][0], acc[r][1], acc[r][2], acc[r][3]);
        float* op = out + ((size_t)(b * CH + co) * P + (r0 + r)) * P + (c0blk + c0);
        *reinterpret_cast<float4*>(op) = v;
    }
}

extern "C" void kernel_launch(void* const* d_in, const int* in_sizes, int n_in,
                              void* d_out, int out_size)
{
    (void)in_sizes; (void)n_in; (void)out_size;
    const float* x    = (const float*)d_in[0];
    const float* rbuf = (const float*)d_in[1];
    const float* bbuf = (const float*)d_in[2];
    const float* Wt   = (const float*)d_in[3];
    const float* bias = (const float*)d_in[4];
    float* out = (float*)d_out;

    static bool inited = false;
    if (!inited) {
        cudaFuncSetAttribute(streamnet_conv3x3_kernel,
                             cudaFuncAttributeMaxDynamicSharedMemorySize, SMEM_BYTES);
        inited = true;
    }

    dim3 grid(P / TW, P / TH, BATCH);   // 8 x 32 x 8 = 2048 blocks
    streamnet_conv3x3_kernel<<<grid, 256, SMEM_BYTES>>>(x, rbuf, bbuf, Wt, bias, out);
}